// round 14
// baseline (speedup 1.0000x reference)
#include <cuda_runtime.h>
#include <cuda_bf16.h>
#include <math.h>
#include <stdint.h>

// Problem constants
#define T_SEQ 2048
#define HID 3584
#define NH 16
#define NKV 8
#define HD 256
#define QKV_N ((NH + 2 * NKV) * HD)   // 8192
#define ATT_N (NH * HD)               // 4096

// Scratch (static device globals — no runtime allocation)
__device__ float g_qkv[(size_t)T_SEQ * QKV_N];    // 64 MB

// bf16 hi/lo splits for tensor-core GEMMs (weights row-major [K][N])
__device__ __nv_bfloat16 g_hid_hi[(size_t)T_SEQ * HID];
__device__ __nv_bfloat16 g_hid_lo[(size_t)T_SEQ * HID];
__device__ __nv_bfloat16 g_wqkv_hi[(size_t)HID * QKV_N];
__device__ __nv_bfloat16 g_wqkv_lo[(size_t)HID * QKV_N];
__device__ __nv_bfloat16 g_wo_hi[(size_t)ATT_N * HID];
__device__ __nv_bfloat16 g_wo_lo[(size_t)ATT_N * HID];
__device__ __nv_bfloat16 g_att_hi[(size_t)T_SEQ * ATT_N];
__device__ __nv_bfloat16 g_att_lo[(size_t)T_SEQ * ATT_N];

// head-major post-RoPE Q/K/V splits for attention: [head][t][d]
__device__ __nv_bfloat16 g_q_hi[(size_t)NH * T_SEQ * HD];
__device__ __nv_bfloat16 g_q_lo[(size_t)NH * T_SEQ * HD];
__device__ __nv_bfloat16 g_k_hi[(size_t)NKV * T_SEQ * HD];
__device__ __nv_bfloat16 g_k_lo[(size_t)NKV * T_SEQ * HD];
__device__ __nv_bfloat16 g_v_hi[(size_t)NKV * T_SEQ * HD];
__device__ __nv_bfloat16 g_v_lo[(size_t)NKV * T_SEQ * HD];

// RoPE cos/sin tables [t][i], i = 0..127
__device__ float g_rope_cos[(size_t)T_SEQ * 128];
__device__ float g_rope_sin[(size_t)T_SEQ * 128];

// ---------------------------------------------------------------------------
// helpers
// ---------------------------------------------------------------------------
__device__ __forceinline__ uint32_t smem_u32(const void* p) {
    return (uint32_t)__cvta_generic_to_shared(p);
}
__device__ __forceinline__ void ldsm_x4(uint32_t* r, uint32_t addr) {
    asm volatile("ldmatrix.sync.aligned.m8n8.x4.shared.b16 {%0,%1,%2,%3}, [%4];\n"
                 : "=r"(r[0]), "=r"(r[1]), "=r"(r[2]), "=r"(r[3]) : "r"(addr));
}
__device__ __forceinline__ void ldsm_x4_t(uint32_t* r, uint32_t addr) {
    asm volatile("ldmatrix.sync.aligned.m8n8.x4.trans.shared.b16 {%0,%1,%2,%3}, [%4];\n"
                 : "=r"(r[0]), "=r"(r[1]), "=r"(r[2]), "=r"(r[3]) : "r"(addr));
}
__device__ __forceinline__ void mma_bf16(float* c, const uint32_t* a, const uint32_t* b) {
    asm volatile(
        "mma.sync.aligned.m16n8k16.row.col.f32.bf16.bf16.f32 "
        "{%0,%1,%2,%3}, {%4,%5,%6,%7}, {%8,%9}, {%0,%1,%2,%3};\n"
        : "+f"(c[0]), "+f"(c[1]), "+f"(c[2]), "+f"(c[3])
        : "r"(a[0]), "r"(a[1]), "r"(a[2]), "r"(a[3]), "r"(b[0]), "r"(b[1]));
}
__device__ __forceinline__ void cp_async16(uint32_t smem_addr, const void* gptr) {
    asm volatile("cp.async.cg.shared.global [%0], [%1], 16;\n"
                 :: "r"(smem_addr), "l"(gptr));
}
__device__ __forceinline__ void cp_commit() {
    asm volatile("cp.async.commit_group;\n");
}
template <int N>
__device__ __forceinline__ void cp_wait() {
    asm volatile("cp.async.wait_group %0;\n" :: "n"(N));
}
__device__ __forceinline__ void split2(float x, __nv_bfloat16& h, __nv_bfloat16& l) {
    h = __float2bfloat16_rn(x);
    l = __float2bfloat16_rn(x - __bfloat162float(h));
}
__device__ __forceinline__ uint32_t pack_bf2(__nv_bfloat16 a, __nv_bfloat16 b) {
    __nv_bfloat162 t;
    t.x = a; t.y = b;
    uint32_t r;
    memcpy(&r, &t, 4);
    return r;
}

// ---------------------------------------------------------------------------
// Split fp32 -> bf16 hi + bf16 lo (residual). n must be multiple of 4.
// ---------------------------------------------------------------------------
__global__ void split_kernel(const float* __restrict__ x,
                             __nv_bfloat16* __restrict__ hi,
                             __nv_bfloat16* __restrict__ lo, size_t n)
{
    size_t i = ((size_t)blockIdx.x * blockDim.x + threadIdx.x) * 4;
    if (i >= n) return;
    float4 v = *(const float4*)(x + i);
    __nv_bfloat16 h[4], l[4];
    float vv[4] = {v.x, v.y, v.z, v.w};
#pragma unroll
    for (int j = 0; j < 4; j++) split2(vv[j], h[j], l[j]);
    *(uint2*)(hi + i) = *(uint2*)h;
    *(uint2*)(lo + i) = *(uint2*)l;
}

// ---------------------------------------------------------------------------
// Wide split-bf16 tensor-core GEMM: 128(M) x 256(N) tile, BK=32, 256 threads,
// 8 warps in 2x4, warp tile 64x64. 2-stage cp.async pipeline.
// ---------------------------------------------------------------------------
#define AS_STRIDE 40
#define WBS_STRIDE 264
#define W_AH 0
#define W_AL (128 * AS_STRIDE)                       // 5120
#define W_BH (2 * 128 * AS_STRIDE)                   // 10240
#define W_BL (2 * 128 * AS_STRIDE + 32 * WBS_STRIDE) // 18688
#define W_STAGE (2 * 128 * AS_STRIDE + 2 * 32 * WBS_STRIDE)  // 27136 elems
#define WGEMM_SMEM_BYTES (2 * W_STAGE * 2)           // 108544 B

__global__ __launch_bounds__(256, 1) void bgemm3w_kernel(
    const __nv_bfloat16* __restrict__ Ahi_g, const __nv_bfloat16* __restrict__ Alo_g,
    const __nv_bfloat16* __restrict__ Bhi_g, const __nv_bfloat16* __restrict__ Blo_g,
    float* __restrict__ C, int M, int N, int K)
{
    extern __shared__ __nv_bfloat16 gs[];

    const int tid = threadIdx.x;
    const int wid = tid >> 5;
    const int lane = tid & 31;
    const int wm = wid & 1;        // 2 warp rows  -> 64 M-rows each
    const int wn = wid >> 1;       // 4 warp cols  -> 64 N-cols each

    const int bm0 = blockIdx.y * 128;
    const int bn0 = blockIdx.x * 256;

    const int NIT = K / 32;

    auto issue_stage = [&](int stage, int k0) {
        __nv_bfloat16* S = gs + stage * W_STAGE;
        const uint32_t sAh = smem_u32(S + W_AH);
        const uint32_t sAl = smem_u32(S + W_AL);
        const uint32_t sBh = smem_u32(S + W_BH);
        const uint32_t sBl = smem_u32(S + W_BL);
#pragma unroll
        for (int j = 0; j < 2; j++) {            // A: 512 chunks
            int ci = tid + j * 256;
            int r = ci >> 2, c = (ci & 3) * 8;
            const size_t g = (size_t)(bm0 + r) * K + k0 + c;
            const uint32_t off = (uint32_t)(r * AS_STRIDE + c) * 2;
            cp_async16(sAh + off, Ahi_g + g);
            cp_async16(sAl + off, Alo_g + g);
        }
#pragma unroll
        for (int j = 0; j < 4; j++) {            // B: 1024 chunks
            int ci = tid + j * 256;
            int r = ci >> 5, c = (ci & 31) * 8;
            const size_t g = (size_t)(k0 + r) * N + bn0 + c;
            const uint32_t off = (uint32_t)(r * WBS_STRIDE + c) * 2;
            cp_async16(sBh + off, Bhi_g + g);
            cp_async16(sBl + off, Blo_g + g);
        }
        cp_commit();
    };

    float c[4][8][4] = {};

    issue_stage(0, 0);

    for (int it = 0; it < NIT; it++) {
        const int s = it & 1;
        if (it + 1 < NIT) issue_stage(s ^ 1, (it + 1) * 32);

        if (it + 1 < NIT) cp_wait<1>(); else cp_wait<0>();
        __syncthreads();

        const __nv_bfloat16* S = gs + s * W_STAGE;
        const __nv_bfloat16* Ah = S + W_AH;
        const __nv_bfloat16* Al = S + W_AL;
        const __nv_bfloat16* Bh = S + W_BH;
        const __nv_bfloat16* Bl = S + W_BL;

#pragma unroll
        for (int ks = 0; ks < 32; ks += 16) {
            uint32_t ah[4][4], al[4][4], bh[8][2], bl[8][2];
            const int arow = wm * 64 + (lane & 15);
            const int acol = ks + (lane >> 4) * 8;
#pragma unroll
            for (int mi = 0; mi < 4; mi++) {
                ldsm_x4(ah[mi], smem_u32(Ah + (arow + mi * 16) * AS_STRIDE + acol));
                ldsm_x4(al[mi], smem_u32(Al + (arow + mi * 16) * AS_STRIDE + acol));
            }
            const int brow = ks + (lane & 15);
#pragma unroll
            for (int nj = 0; nj < 4; nj++) {
                const int bcol = wn * 64 + nj * 16 + (lane >> 4) * 8;
                uint32_t r[4];
                ldsm_x4_t(r, smem_u32(Bh + brow * WBS_STRIDE + bcol));
                bh[nj * 2][0] = r[0]; bh[nj * 2][1] = r[1];
                bh[nj * 2 + 1][0] = r[2]; bh[nj * 2 + 1][1] = r[3];
                ldsm_x4_t(r, smem_u32(Bl + brow * WBS_STRIDE + bcol));
                bl[nj * 2][0] = r[0]; bl[nj * 2][1] = r[1];
                bl[nj * 2 + 1][0] = r[2]; bl[nj * 2 + 1][1] = r[3];
            }
#pragma unroll
            for (int mi = 0; mi < 4; mi++)
#pragma unroll
                for (int ni = 0; ni < 8; ni++) {
                    mma_bf16(c[mi][ni], ah[mi], bh[ni]);
                    mma_bf16(c[mi][ni], ah[mi], bl[ni]);
                    mma_bf16(c[mi][ni], al[mi], bh[ni]);
                }
        }
        __syncthreads();
    }

    const int gid = lane >> 2, tig = lane & 3;
#pragma unroll
    for (int mi = 0; mi < 4; mi++) {
        const int r0 = bm0 + wm * 64 + mi * 16 + gid;
#pragma unroll
        for (int ni = 0; ni < 8; ni++) {
            const int cc = bn0 + wn * 64 + ni * 8 + tig * 2;
            *(float2*)&C[(size_t)r0 * N + cc] = make_float2(c[mi][ni][0], c[mi][ni][1]);
            *(float2*)&C[(size_t)(r0 + 8) * N + cc] = make_float2(c[mi][ni][2], c[mi][ni][3]);
        }
    }
}

// ---------------------------------------------------------------------------
// RoPE table: one sincos per (t, i) — removes the 24x duplicate transcendental
// work that rope_split used to do per head.
// ---------------------------------------------------------------------------
__global__ void rope_table_kernel(const int* __restrict__ positions)
{
    const int t = blockIdx.x;
    const int i = threadIdx.x;   // 0..127
    const float pos = (float)positions[t];
    const float inv_freq = powf(10000.0f, -(float)i * (1.0f / 128.0f));
    float s, c;
    sincosf(pos * inv_freq, &s, &c);
    g_rope_cos[(size_t)t * 128 + i] = c;
    g_rope_sin[(size_t)t * 128 + i] = s;
}

// ---------------------------------------------------------------------------
// RoPE + split: read fp32 qkv, rotate q/k using the table (v passthrough),
// write bf16 hi/lo head-major arrays [head][t][d].
// ---------------------------------------------------------------------------
__global__ void rope_split_kernel()
{
    const int t = blockIdx.x;
    const int hh = blockIdx.y;
    const int i = threadIdx.x;

    float y1, y2;
    __nv_bfloat16 *dst_hi, *dst_lo;

    if (hh < NH + NKV) {
        const int head_off = (hh < NH) ? hh : (NH + (hh - NH));
        const float* src = g_qkv + (size_t)t * QKV_N + head_off * HD;
        const float c = g_rope_cos[(size_t)t * 128 + i];
        const float s = g_rope_sin[(size_t)t * 128 + i];
        const float x1 = src[i];
        const float x2 = src[i + 128];
        y1 = x1 * c - x2 * s;
        y2 = x2 * c + x1 * s;
        if (hh < NH) {
            dst_hi = g_q_hi + ((size_t)hh * T_SEQ + t) * HD;
            dst_lo = g_q_lo + ((size_t)hh * T_SEQ + t) * HD;
        } else {
            const int kvh = hh - NH;
            dst_hi = g_k_hi + ((size_t)kvh * T_SEQ + t) * HD;
            dst_lo = g_k_lo + ((size_t)kvh * T_SEQ + t) * HD;
        }
    } else {
        const int vh = hh - (NH + NKV);
        const float* src = g_qkv + (size_t)t * QKV_N + (NH + NKV + vh) * HD;
        y1 = src[i];
        y2 = src[i + 128];
        dst_hi = g_v_hi + ((size_t)vh * T_SEQ + t) * HD;
        dst_lo = g_v_lo + ((size_t)vh * T_SEQ + t) * HD;
    }

    __nv_bfloat16 h1, l1, h2, l2;
    split2(y1, h1, l1);
    split2(y2, h2, l2);
    dst_hi[i] = h1;        dst_lo[i] = l1;
    dst_hi[i + 128] = h2;  dst_lo[i + 128] = l2;
}

// ---------------------------------------------------------------------------
// Tensor-core flash attention (split-bf16) with 2-stage cp.async K/V pipeline
// (unchanged from R12).
// ---------------------------------------------------------------------------
#define ATS 264
#define AQ_TILE (64 * ATS)
#define AKV_TILE (32 * ATS)
#define ATT2_SMEM_BYTES ((2 * AQ_TILE + 8 * AKV_TILE) * 2)   // 202752

__global__ __launch_bounds__(128, 1) void attn_mma_kernel()
{
    extern __shared__ __nv_bfloat16 sb[];
    __nv_bfloat16* SQh = sb;
    __nv_bfloat16* SQl = sb + AQ_TILE;

    const int tid = threadIdx.x;
    const int lane = tid & 31;
    const int warp = tid >> 5;
    const int qt = (int)gridDim.x - 1 - (int)blockIdx.x;
    const int h = blockIdx.y;
    const int kvh = h >> 1;
    const int q0 = qt * 64;

    {
        const __nv_bfloat16* gqh = g_q_hi + ((size_t)h * T_SEQ + q0) * HD;
        const __nv_bfloat16* gql = g_q_lo + ((size_t)h * T_SEQ + q0) * HD;
        for (int it = tid; it < 64 * 32; it += 128) {
            int r = it >> 5, c = (it & 31) * 8;
            *(float4*)&SQh[r * ATS + c] = *(const float4*)(gqh + (size_t)r * HD + c);
            *(float4*)&SQl[r * ATS + c] = *(const float4*)(gql + (size_t)r * HD + c);
        }
    }

    float acc[32][4];
#pragma unroll
    for (int n = 0; n < 32; n++)
#pragma unroll
        for (int e = 0; e < 4; e++) acc[n][e] = 0.0f;
    float m0 = -INFINITY, m1 = -INFINITY, l0 = 0.0f, l1 = 0.0f;

    const float cap_mul = 0.0625f / 50.0f;

    const int qrow = warp * 16 + (lane & 15);
    const int qc8 = (lane >> 4) << 3;
    const int krow_b = ((lane >> 4) << 3) + (lane & 7);
    const int kc8 = ((lane >> 3) & 1) << 3;
    const int vrow_b = lane & 15;
    const int vc8 = (lane >> 4) << 3;

    const __nv_bfloat16* gkh = g_k_hi + (size_t)kvh * T_SEQ * HD;
    const __nv_bfloat16* gkl = g_k_lo + (size_t)kvh * T_SEQ * HD;
    const __nv_bfloat16* gvh = g_v_hi + (size_t)kvh * T_SEQ * HD;
    const __nv_bfloat16* gvl = g_v_lo + (size_t)kvh * T_SEQ * HD;

    const int NKT = 2 * (qt + 1);

    auto issue_kv = [&](int t) {
        __nv_bfloat16* S = sb + 2 * AQ_TILE + (size_t)(t & 1) * 4 * AKV_TILE;
        const uint32_t skh = smem_u32(S);
        const uint32_t skl = smem_u32(S + AKV_TILE);
        const uint32_t svh = smem_u32(S + 2 * AKV_TILE);
        const uint32_t svl = smem_u32(S + 3 * AKV_TILE);
        const int k0 = t * 32;
#pragma unroll
        for (int i = 0; i < 8; i++) {
            int it = tid + i * 128;
            int r = it >> 5, c = (it & 31) * 8;
            const size_t g = (size_t)(k0 + r) * HD + c;
            const uint32_t off = (uint32_t)(r * ATS + c) * 2;
            cp_async16(skh + off, gkh + g);
            cp_async16(skl + off, gkl + g);
            cp_async16(svh + off, gvh + g);
            cp_async16(svl + off, gvl + g);
        }
        cp_commit();
    };

    issue_kv(0);

    for (int t = 0; t < NKT; t++) {
        if (t + 1 < NKT) { issue_kv(t + 1); cp_wait<1>(); }
        else             { cp_wait<0>(); }
        __syncthreads();

        __nv_bfloat16* S = sb + 2 * AQ_TILE + (size_t)(t & 1) * 4 * AKV_TILE;
        __nv_bfloat16* SKh = S;
        __nv_bfloat16* SKl = S + AKV_TILE;
        __nv_bfloat16* SVh = S + 2 * AKV_TILE;
        __nv_bfloat16* SVl = S + 3 * AKV_TILE;
        const int k0 = t * 32;

        float sc[4][4];
#pragma unroll
        for (int n = 0; n < 4; n++)
#pragma unroll
            for (int e = 0; e < 4; e++) sc[n][e] = 0.0f;

#pragma unroll 4
        for (int ks = 0; ks < HD; ks += 16) {
            uint32_t aqh[4], aql[4];
            ldsm_x4(aqh, smem_u32(&SQh[qrow * ATS + ks + qc8]));
            ldsm_x4(aql, smem_u32(&SQl[qrow * ATS + ks + qc8]));
#pragma unroll
            for (int p4 = 0; p4 < 2; p4++) {
                uint32_t bh[4], bl[4];
                const int kr = p4 * 16 + krow_b;
                ldsm_x4(bh, smem_u32(&SKh[kr * ATS + ks + kc8]));
                ldsm_x4(bl, smem_u32(&SKl[kr * ATS + ks + kc8]));
                mma_bf16(sc[2 * p4], aqh, bh);
                mma_bf16(sc[2 * p4], aqh, bl);
                mma_bf16(sc[2 * p4], aql, bh);
                mma_bf16(sc[2 * p4 + 1], aqh, bh + 2);
                mma_bf16(sc[2 * p4 + 1], aqh, bl + 2);
                mma_bf16(sc[2 * p4 + 1], aql, bh + 2);
            }
        }

        const bool diag = (t >= NKT - 2);
        const int colb = k0 + 2 * (lane & 3);
        const int rowg = q0 + warp * 16 + (lane >> 2);
#pragma unroll
        for (int nt = 0; nt < 4; nt++) {
#pragma unroll
            for (int e = 0; e < 4; e++) {
                float z = 50.0f * tanhf(sc[nt][e] * cap_mul);
                if (diag) {
                    int col = colb + nt * 8 + (e & 1);
                    int row = rowg + ((e >> 1) << 3);
                    if (col > row) z = -INFINITY;
                }
                sc[nt][e] = z;
            }
        }

        float rm0 = -INFINITY, rm1 = -INFINITY;
#pragma unroll
        for (int nt = 0; nt < 4; nt++) {
            rm0 = fmaxf(rm0, fmaxf(sc[nt][0], sc[nt][1]));
            rm1 = fmaxf(rm1, fmaxf(sc[nt][2], sc[nt][3]));
        }
        rm0 = fmaxf(rm0, __shfl_xor_sync(0xffffffffu, rm0, 1));
        rm0 = fmaxf(rm0, __shfl_xor_sync(0xffffffffu, rm0, 2));
        rm1 = fmaxf(rm1, __shfl_xor_sync(0xffffffffu, rm1, 1));
        rm1 = fmaxf(rm1, __shfl_xor_sync(0xffffffffu, rm1, 2));

        const float nm0 = fmaxf(m0, rm0);
        const float nm1 = fmaxf(m1, rm1);
        const float cr0 = __expf(m0 - nm0);
        const float cr1 = __expf(m1 - nm1);

        float ps0 = 0.0f, ps1 = 0.0f;
#pragma unroll
        for (int nt = 0; nt < 4; nt++) {
            float p0 = __expf(sc[nt][0] - nm0);
            float p1 = __expf(sc[nt][1] - nm0);
            float p2 = __expf(sc[nt][2] - nm1);
            float p3 = __expf(sc[nt][3] - nm1);
            sc[nt][0] = p0; sc[nt][1] = p1; sc[nt][2] = p2; sc[nt][3] = p3;
            ps0 += p0 + p1;
            ps1 += p2 + p3;
        }
        ps0 += __shfl_xor_sync(0xffffffffu, ps0, 1);
        ps0 += __shfl_xor_sync(0xffffffffu, ps0, 2);
        ps1 += __shfl_xor_sync(0xffffffffu, ps1, 1);
        ps1 += __shfl_xor_sync(0xffffffffu, ps1, 2);

        l0 = l0 * cr0 + ps0;
        l1 = l1 * cr1 + ps1;
        m0 = nm0; m1 = nm1;

#pragma unroll
        for (int n = 0; n < 32; n++) {
            acc[n][0] *= cr0; acc[n][1] *= cr0;
            acc[n][2] *= cr1; acc[n][3] *= cr1;
        }

        uint32_t ph[2][4], pl[2][4];
#pragma unroll
        for (int j = 0; j < 2; j++) {
            __nv_bfloat16 h0, lo0, h1, lo1;
#pragma unroll
            for (int half = 0; half < 2; half++) {
                const int nt = 2 * j + half;
                split2(sc[nt][0], h0, lo0);
                split2(sc[nt][1], h1, lo1);
                ph[j][2 * half] = pack_bf2(h0, h1);
                pl[j][2 * half] = pack_bf2(lo0, lo1);
                split2(sc[nt][2], h0, lo0);
                split2(sc[nt][3], h1, lo1);
                ph[j][2 * half + 1] = pack_bf2(h0, h1);
                pl[j][2 * half + 1] = pack_bf2(lo0, lo1);
            }
        }

#pragma unroll
        for (int kk = 0; kk < 2; kk++) {
            const int vr = kk * 16 + vrow_b;
#pragma unroll
            for (int np = 0; np < 16; np++) {
                uint32_t bvh[4], bvl[4];
                const int vc = np * 16 + vc8;
                ldsm_x4_t(bvh, smem_u32(&SVh[vr * ATS + vc]));
                ldsm_x4_t(bvl, smem_u32(&SVl[vr * ATS + vc]));
                mma_bf16(acc[2 * np], ph[kk], bvh);
                mma_bf16(acc[2 * np], ph[kk], bvl);
                mma_bf16(acc[2 * np], pl[kk], bvh);
                mma_bf16(acc[2 * np + 1], ph[kk], bvh + 2);
                mma_bf16(acc[2 * np + 1], ph[kk], bvl + 2);
                mma_bf16(acc[2 * np + 1], pl[kk], bvh + 2);
            }
        }
        __syncthreads();
    }

    const float il0 = 1.0f / l0;
    const float il1 = 1.0f / l1;
    const size_t rowA = (size_t)(q0 + warp * 16 + (lane >> 2));
    const size_t rowB = rowA + 8;
    const int cb = h * HD + 2 * (lane & 3);
#pragma unroll
    for (int nt = 0; nt < 32; nt++) {
        const int c = cb + nt * 8;
        float o0 = acc[nt][0] * il0, o1 = acc[nt][1] * il0;
        float o2 = acc[nt][2] * il1, o3 = acc[nt][3] * il1;
        __nv_bfloat16 h0, lo0, h1, lo1;
        split2(o0, h0, lo0); split2(o1, h1, lo1);
        *(uint32_t*)&g_att_hi[rowA * ATT_N + c] = pack_bf2(h0, h1);
        *(uint32_t*)&g_att_lo[rowA * ATT_N + c] = pack_bf2(lo0, lo1);
        split2(o2, h0, lo0); split2(o3, h1, lo1);
        *(uint32_t*)&g_att_hi[rowB * ATT_N + c] = pack_bf2(h0, h1);
        *(uint32_t*)&g_att_lo[rowB * ATT_N + c] = pack_bf2(lo0, lo1);
    }
}

// ---------------------------------------------------------------------------
// kernel_launch
// ---------------------------------------------------------------------------
extern "C" void kernel_launch(void* const* d_in, const int* in_sizes, int n_in,
                              void* d_out, int out_size)
{
    const int*   positions = (const int*)d_in[0];
    const float* hidden    = (const float*)d_in[1];
    const float* w_qkv     = (const float*)d_in[2];
    const float* w_o       = (const float*)d_in[3];
    float* out = (float*)d_out;

    float* qkv_ptr = nullptr;
    __nv_bfloat16 *hid_hi, *hid_lo, *wqkv_hi, *wqkv_lo, *wo_hi, *wo_lo, *att_hi, *att_lo;
    cudaGetSymbolAddress((void**)&qkv_ptr, g_qkv);
    cudaGetSymbolAddress((void**)&hid_hi, g_hid_hi);
    cudaGetSymbolAddress((void**)&hid_lo, g_hid_lo);
    cudaGetSymbolAddress((void**)&wqkv_hi, g_wqkv_hi);
    cudaGetSymbolAddress((void**)&wqkv_lo, g_wqkv_lo);
    cudaGetSymbolAddress((void**)&wo_hi, g_wo_hi);
    cudaGetSymbolAddress((void**)&wo_lo, g_wo_lo);
    cudaGetSymbolAddress((void**)&att_hi, g_att_hi);
    cudaGetSymbolAddress((void**)&att_lo, g_att_lo);

    // 0) Split inputs into bf16 hi/lo; build RoPE table
    {
        size_t n1 = (size_t)T_SEQ * HID;
        split_kernel<<<(unsigned)((n1 / 4 + 255) / 256), 256>>>(hidden, hid_hi, hid_lo, n1);
        size_t n2 = (size_t)HID * QKV_N;
        split_kernel<<<(unsigned)((n2 / 4 + 255) / 256), 256>>>(w_qkv, wqkv_hi, wqkv_lo, n2);
        size_t n3 = (size_t)ATT_N * HID;
        split_kernel<<<(unsigned)((n3 / 4 + 255) / 256), 256>>>(w_o, wo_hi, wo_lo, n3);
        rope_table_kernel<<<T_SEQ, 128>>>(positions);
    }

    // 1) QKV projection (wide pipelined split-bf16 tensor GEMM)
    {
        cudaFuncSetAttribute(bgemm3w_kernel,
                             cudaFuncAttributeMaxDynamicSharedMemorySize,
                             WGEMM_SMEM_BYTES);
        dim3 grid(QKV_N / 256, T_SEQ / 128);   // (32, 16)
        bgemm3w_kernel<<<grid, 256, WGEMM_SMEM_BYTES>>>(
            hid_hi, hid_lo, wqkv_hi, wqkv_lo, qkv_ptr, T_SEQ, QKV_N, HID);
    }

    // 2) RoPE + split to head-major bf16 hi/lo Q/K/V
    rope_split_kernel<<<dim3(T_SEQ, NH + 2 * NKV), 128>>>();

    // 3) Pipelined tensor-core flash attention -> att_hi/att_lo
    {
        cudaFuncSetAttribute(attn_mma_kernel,
                             cudaFuncAttributeMaxDynamicSharedMemorySize,
                             ATT2_SMEM_BYTES);
        attn_mma_kernel<<<dim3(T_SEQ / 64, NH), 128, ATT2_SMEM_BYTES>>>();
    }

    // 4) O projection (wide pipelined split-bf16 tensor GEMM)
    {
        dim3 grid(HID / 256, T_SEQ / 128);     // (14, 16)
        bgemm3w_kernel<<<grid, 256, WGEMM_SMEM_BYTES>>>(
            att_hi, att_lo, wo_hi, wo_lo, out, T_SEQ, HID, ATT_N);
    }
}

// round 15
// speedup vs baseline: 1.1297x; 1.1297x over previous
#include <cuda_runtime.h>
#include <cuda_bf16.h>
#include <math.h>
#include <stdint.h>

// Problem constants
#define T_SEQ 2048
#define HID 3584
#define NH 16
#define NKV 8
#define HD 256
#define QKV_N ((NH + 2 * NKV) * HD)   // 8192
#define ATT_N (NH * HD)               // 4096

// Scratch (static device globals — no runtime allocation)
__device__ float g_qkv[(size_t)T_SEQ * QKV_N];    // 64 MB

// bf16 hi/lo splits for tensor-core GEMMs (weights row-major [K][N])
__device__ __nv_bfloat16 g_hid_hi[(size_t)T_SEQ * HID];
__device__ __nv_bfloat16 g_hid_lo[(size_t)T_SEQ * HID];
__device__ __nv_bfloat16 g_wqkv_hi[(size_t)HID * QKV_N];
__device__ __nv_bfloat16 g_wqkv_lo[(size_t)HID * QKV_N];
__device__ __nv_bfloat16 g_wo_hi[(size_t)ATT_N * HID];
__device__ __nv_bfloat16 g_wo_lo[(size_t)ATT_N * HID];
__device__ __nv_bfloat16 g_att_hi[(size_t)T_SEQ * ATT_N];
__device__ __nv_bfloat16 g_att_lo[(size_t)T_SEQ * ATT_N];

// head-major post-RoPE Q/K/V splits for attention: [head][t][d]
__device__ __nv_bfloat16 g_q_hi[(size_t)NH * T_SEQ * HD];
__device__ __nv_bfloat16 g_q_lo[(size_t)NH * T_SEQ * HD];
__device__ __nv_bfloat16 g_k_hi[(size_t)NKV * T_SEQ * HD];
__device__ __nv_bfloat16 g_k_lo[(size_t)NKV * T_SEQ * HD];
__device__ __nv_bfloat16 g_v_hi[(size_t)NKV * T_SEQ * HD];
__device__ __nv_bfloat16 g_v_lo[(size_t)NKV * T_SEQ * HD];

// RoPE cos/sin tables [t][i], i = 0..127
__device__ float g_rope_cos[(size_t)T_SEQ * 128];
__device__ float g_rope_sin[(size_t)T_SEQ * 128];

// ---------------------------------------------------------------------------
// helpers
// ---------------------------------------------------------------------------
__device__ __forceinline__ uint32_t smem_u32(const void* p) {
    return (uint32_t)__cvta_generic_to_shared(p);
}
__device__ __forceinline__ void ldsm_x4(uint32_t* r, uint32_t addr) {
    asm volatile("ldmatrix.sync.aligned.m8n8.x4.shared.b16 {%0,%1,%2,%3}, [%4];\n"
                 : "=r"(r[0]), "=r"(r[1]), "=r"(r[2]), "=r"(r[3]) : "r"(addr));
}
__device__ __forceinline__ void ldsm_x4_t(uint32_t* r, uint32_t addr) {
    asm volatile("ldmatrix.sync.aligned.m8n8.x4.trans.shared.b16 {%0,%1,%2,%3}, [%4];\n"
                 : "=r"(r[0]), "=r"(r[1]), "=r"(r[2]), "=r"(r[3]) : "r"(addr));
}
__device__ __forceinline__ void mma_bf16(float* c, const uint32_t* a, const uint32_t* b) {
    asm volatile(
        "mma.sync.aligned.m16n8k16.row.col.f32.bf16.bf16.f32 "
        "{%0,%1,%2,%3}, {%4,%5,%6,%7}, {%8,%9}, {%0,%1,%2,%3};\n"
        : "+f"(c[0]), "+f"(c[1]), "+f"(c[2]), "+f"(c[3])
        : "r"(a[0]), "r"(a[1]), "r"(a[2]), "r"(a[3]), "r"(b[0]), "r"(b[1]));
}
__device__ __forceinline__ void cp_async16(uint32_t smem_addr, const void* gptr) {
    asm volatile("cp.async.cg.shared.global [%0], [%1], 16;\n"
                 :: "r"(smem_addr), "l"(gptr));
}
__device__ __forceinline__ void cp_commit() {
    asm volatile("cp.async.commit_group;\n");
}
template <int N>
__device__ __forceinline__ void cp_wait() {
    asm volatile("cp.async.wait_group %0;\n" :: "n"(N));
}
__device__ __forceinline__ void split2(float x, __nv_bfloat16& h, __nv_bfloat16& l) {
    h = __float2bfloat16_rn(x);
    l = __float2bfloat16_rn(x - __bfloat162float(h));
}
__device__ __forceinline__ uint32_t pack_bf2(__nv_bfloat16 a, __nv_bfloat16 b) {
    __nv_bfloat162 t;
    t.x = a; t.y = b;
    uint32_t r;
    memcpy(&r, &t, 4);
    return r;
}

// ---------------------------------------------------------------------------
// Split fp32 -> bf16 hi + bf16 lo (residual). n must be multiple of 4.
// ---------------------------------------------------------------------------
__global__ void split_kernel(const float* __restrict__ x,
                             __nv_bfloat16* __restrict__ hi,
                             __nv_bfloat16* __restrict__ lo, size_t n)
{
    size_t i = ((size_t)blockIdx.x * blockDim.x + threadIdx.x) * 4;
    if (i >= n) return;
    float4 v = *(const float4*)(x + i);
    __nv_bfloat16 h[4], l[4];
    float vv[4] = {v.x, v.y, v.z, v.w};
#pragma unroll
    for (int j = 0; j < 4; j++) split2(vv[j], h[j], l[j]);
    *(uint2*)(hi + i) = *(uint2*)h;
    *(uint2*)(lo + i) = *(uint2*)l;
}

// ---------------------------------------------------------------------------
// Split-bf16 tensor-core GEMM with 2-stage cp.async pipeline (R12, proven).
// 128x128 tile, BK=32, 256 threads, warp tile 64x32.
// ---------------------------------------------------------------------------
#define AS_STRIDE 40
#define BS_STRIDE 136
#define G_AH 0
#define G_AL (128 * AS_STRIDE)
#define G_BH (2 * 128 * AS_STRIDE)
#define G_BL (2 * 128 * AS_STRIDE + 32 * BS_STRIDE)
#define G_STAGE (2 * 128 * AS_STRIDE + 2 * 32 * BS_STRIDE)
#define GEMM_SMEM_BYTES (2 * G_STAGE * 2)

__global__ __launch_bounds__(256) void bgemm3_kernel(
    const __nv_bfloat16* __restrict__ Ahi_g, const __nv_bfloat16* __restrict__ Alo_g,
    const __nv_bfloat16* __restrict__ Bhi_g, const __nv_bfloat16* __restrict__ Blo_g,
    float* __restrict__ C, int M, int N, int K)
{
    extern __shared__ __nv_bfloat16 gs[];

    const int tid = threadIdx.x;
    const int wid = tid >> 5;
    const int lane = tid & 31;
    const int wm = wid & 1;
    const int wn = wid >> 1;

    const int bm0 = blockIdx.y * 128;
    const int bn0 = blockIdx.x * 128;

    const int ch0 = tid, ch1 = tid + 256;
    const int ar0 = ch0 >> 2, ac0 = (ch0 & 3) * 8;
    const int ar1 = ch1 >> 2, ac1 = (ch1 & 3) * 8;
    const int br0 = ch0 >> 4, bc0 = (ch0 & 15) * 8;
    const int br1 = ch1 >> 4, bc1 = (ch1 & 15) * 8;

    const int NIT = K / 32;

    auto issue_stage = [&](int stage, int k0) {
        __nv_bfloat16* S = gs + stage * G_STAGE;
        uint32_t sAh = smem_u32(S + G_AH);
        uint32_t sAl = smem_u32(S + G_AL);
        uint32_t sBh = smem_u32(S + G_BH);
        uint32_t sBl = smem_u32(S + G_BL);
        cp_async16(sAh + (ar0 * AS_STRIDE + ac0) * 2, Ahi_g + (size_t)(bm0 + ar0) * K + k0 + ac0);
        cp_async16(sAh + (ar1 * AS_STRIDE + ac1) * 2, Ahi_g + (size_t)(bm0 + ar1) * K + k0 + ac1);
        cp_async16(sAl + (ar0 * AS_STRIDE + ac0) * 2, Alo_g + (size_t)(bm0 + ar0) * K + k0 + ac0);
        cp_async16(sAl + (ar1 * AS_STRIDE + ac1) * 2, Alo_g + (size_t)(bm0 + ar1) * K + k0 + ac1);
        cp_async16(sBh + (br0 * BS_STRIDE + bc0) * 2, Bhi_g + (size_t)(k0 + br0) * N + bn0 + bc0);
        cp_async16(sBh + (br1 * BS_STRIDE + bc1) * 2, Bhi_g + (size_t)(k0 + br1) * N + bn0 + bc1);
        cp_async16(sBl + (br0 * BS_STRIDE + bc0) * 2, Blo_g + (size_t)(k0 + br0) * N + bn0 + bc0);
        cp_async16(sBl + (br1 * BS_STRIDE + bc1) * 2, Blo_g + (size_t)(k0 + br1) * N + bn0 + bc1);
        cp_commit();
    };

    float c[4][4][4] = {};

    issue_stage(0, 0);

    for (int it = 0; it < NIT; it++) {
        const int s = it & 1;
        if (it + 1 < NIT) issue_stage(s ^ 1, (it + 1) * 32);

        if (it + 1 < NIT) cp_wait<1>(); else cp_wait<0>();
        __syncthreads();

        const __nv_bfloat16* S = gs + s * G_STAGE;
        const __nv_bfloat16* Ah = S + G_AH;
        const __nv_bfloat16* Al = S + G_AL;
        const __nv_bfloat16* Bh = S + G_BH;
        const __nv_bfloat16* Bl = S + G_BL;

#pragma unroll
        for (int ks = 0; ks < 32; ks += 16) {
            uint32_t ah[4][4], al[4][4], bh[4][2], bl[4][2];
            const int arow = wm * 64 + (lane & 15);
            const int acol = ks + (lane >> 4) * 8;
#pragma unroll
            for (int mi = 0; mi < 4; mi++) {
                ldsm_x4(ah[mi], smem_u32(Ah + (arow + mi * 16) * AS_STRIDE + acol));
                ldsm_x4(al[mi], smem_u32(Al + (arow + mi * 16) * AS_STRIDE + acol));
            }
            const int brow = ks + (lane & 15);
#pragma unroll
            for (int nj = 0; nj < 2; nj++) {
                const int bcol = wn * 32 + nj * 16 + (lane >> 4) * 8;
                uint32_t r[4];
                ldsm_x4_t(r, smem_u32(Bh + brow * BS_STRIDE + bcol));
                bh[nj * 2][0] = r[0]; bh[nj * 2][1] = r[1];
                bh[nj * 2 + 1][0] = r[2]; bh[nj * 2 + 1][1] = r[3];
                ldsm_x4_t(r, smem_u32(Bl + brow * BS_STRIDE + bcol));
                bl[nj * 2][0] = r[0]; bl[nj * 2][1] = r[1];
                bl[nj * 2 + 1][0] = r[2]; bl[nj * 2 + 1][1] = r[3];
            }
#pragma unroll
            for (int mi = 0; mi < 4; mi++)
#pragma unroll
                for (int ni = 0; ni < 4; ni++) {
                    mma_bf16(c[mi][ni], ah[mi], bh[ni]);
                    mma_bf16(c[mi][ni], ah[mi], bl[ni]);
                    mma_bf16(c[mi][ni], al[mi], bh[ni]);
                }
        }
        __syncthreads();
    }

    const int gid = lane >> 2, tig = lane & 3;
#pragma unroll
    for (int mi = 0; mi < 4; mi++) {
        const int r0 = bm0 + wm * 64 + mi * 16 + gid;
#pragma unroll
        for (int ni = 0; ni < 4; ni++) {
            const int cc = bn0 + wn * 32 + ni * 8 + tig * 2;
            *(float2*)&C[(size_t)r0 * N + cc] = make_float2(c[mi][ni][0], c[mi][ni][1]);
            *(float2*)&C[(size_t)(r0 + 8) * N + cc] = make_float2(c[mi][ni][2], c[mi][ni][3]);
        }
    }
}

// ---------------------------------------------------------------------------
// RoPE table: one sincos per (t, i).
// ---------------------------------------------------------------------------
__global__ void rope_table_kernel(const int* __restrict__ positions)
{
    const int t = blockIdx.x;
    const int i = threadIdx.x;
    const float pos = (float)positions[t];
    const float inv_freq = powf(10000.0f, -(float)i * (1.0f / 128.0f));
    float s, c;
    sincosf(pos * inv_freq, &s, &c);
    g_rope_cos[(size_t)t * 128 + i] = c;
    g_rope_sin[(size_t)t * 128 + i] = s;
}

// ---------------------------------------------------------------------------
// RoPE + split to head-major bf16 hi/lo Q/K/V (table-driven).
// ---------------------------------------------------------------------------
__global__ void rope_split_kernel()
{
    const int t = blockIdx.x;
    const int hh = blockIdx.y;
    const int i = threadIdx.x;

    float y1, y2;
    __nv_bfloat16 *dst_hi, *dst_lo;

    if (hh < NH + NKV) {
        const int head_off = (hh < NH) ? hh : (NH + (hh - NH));
        const float* src = g_qkv + (size_t)t * QKV_N + head_off * HD;
        const float c = g_rope_cos[(size_t)t * 128 + i];
        const float s = g_rope_sin[(size_t)t * 128 + i];
        const float x1 = src[i];
        const float x2 = src[i + 128];
        y1 = x1 * c - x2 * s;
        y2 = x2 * c + x1 * s;
        if (hh < NH) {
            dst_hi = g_q_hi + ((size_t)hh * T_SEQ + t) * HD;
            dst_lo = g_q_lo + ((size_t)hh * T_SEQ + t) * HD;
        } else {
            const int kvh = hh - NH;
            dst_hi = g_k_hi + ((size_t)kvh * T_SEQ + t) * HD;
            dst_lo = g_k_lo + ((size_t)kvh * T_SEQ + t) * HD;
        }
    } else {
        const int vh = hh - (NH + NKV);
        const float* src = g_qkv + (size_t)t * QKV_N + (NH + NKV + vh) * HD;
        y1 = src[i];
        y2 = src[i + 128];
        dst_hi = g_v_hi + ((size_t)vh * T_SEQ + t) * HD;
        dst_lo = g_v_lo + ((size_t)vh * T_SEQ + t) * HD;
    }

    __nv_bfloat16 h1, l1, h2, l2;
    split2(y1, h1, l1);
    split2(y2, h2, l2);
    dst_hi[i] = h1;        dst_lo[i] = l1;
    dst_hi[i + 128] = h2;  dst_lo[i + 128] = l2;
}

// ---------------------------------------------------------------------------
// Tensor-core flash attention, 2 GQA heads per CTA sharing KV.
// 256 threads = 8 warps: warps 0-3 -> head 2*kvh, warps 4-7 -> head 2*kvh+1.
// Each warp owns 16 q-rows of its head. KV tiles = 16 keys, double-buffered
// cp.async. smem = 202752 B.
// ---------------------------------------------------------------------------
#define ATS 264
#define AQ_TILE (64 * ATS)          // per hi/lo array per head
#define AKV16 (16 * ATS)            // per array per stage
#define ATT2_SMEM_BYTES ((4 * AQ_TILE + 8 * AKV16) * 2)   // 202752

__global__ __launch_bounds__(256, 1) void attn_mma_kernel()
{
    extern __shared__ __nv_bfloat16 sb[];

    const int tid = threadIdx.x;
    const int lane = tid & 31;
    const int warp = tid >> 5;
    const int hsel = warp >> 2;          // 0 or 1: which head in the pair
    const int wq = warp & 3;             // q-row group within head
    const int qt = (int)gridDim.x - 1 - (int)blockIdx.x;
    const int kvh = blockIdx.y;
    const int h = 2 * kvh + hsel;
    const int q0 = qt * 64;

    __nv_bfloat16* SQh = sb + (size_t)hsel * 2 * AQ_TILE;
    __nv_bfloat16* SQl = SQh + AQ_TILE;
    __nv_bfloat16* KVbase = sb + 4 * AQ_TILE;

    // ---- load both heads' Q tiles ----
#pragma unroll
    for (int hh2 = 0; hh2 < 2; hh2++) {
        const __nv_bfloat16* gqh = g_q_hi + ((size_t)(2 * kvh + hh2) * T_SEQ + q0) * HD;
        const __nv_bfloat16* gql = g_q_lo + ((size_t)(2 * kvh + hh2) * T_SEQ + q0) * HD;
        __nv_bfloat16* dh = sb + (size_t)hh2 * 2 * AQ_TILE;
        __nv_bfloat16* dl = dh + AQ_TILE;
        for (int it = tid; it < 64 * 32; it += 256) {
            int r = it >> 5, c = (it & 31) * 8;
            *(float4*)&dh[r * ATS + c] = *(const float4*)(gqh + (size_t)r * HD + c);
            *(float4*)&dl[r * ATS + c] = *(const float4*)(gql + (size_t)r * HD + c);
        }
    }

    float acc[32][4];
#pragma unroll
    for (int n = 0; n < 32; n++)
#pragma unroll
        for (int e = 0; e < 4; e++) acc[n][e] = 0.0f;
    float m0 = -INFINITY, m1 = -INFINITY, l0 = 0.0f, l1 = 0.0f;

    const float cap_mul = 0.0625f / 50.0f;   // SCALE / SOFT_CAP

    const int qrow = wq * 16 + (lane & 15);
    const int qc8 = (lane >> 4) << 3;
    const int krow_b = ((lane >> 4) << 3) + (lane & 7);   // 0..15
    const int kc8 = ((lane >> 3) & 1) << 3;
    const int vrow_b = lane & 15;
    const int vc8 = (lane >> 4) << 3;

    const __nv_bfloat16* gkh = g_k_hi + (size_t)kvh * T_SEQ * HD;
    const __nv_bfloat16* gkl = g_k_lo + (size_t)kvh * T_SEQ * HD;
    const __nv_bfloat16* gvh = g_v_hi + (size_t)kvh * T_SEQ * HD;
    const __nv_bfloat16* gvl = g_v_lo + (size_t)kvh * T_SEQ * HD;

    const int NKT = 4 * (qt + 1);   // 16-key tiles

    auto issue_kv = [&](int t) {
        __nv_bfloat16* S = KVbase + (size_t)(t & 1) * 4 * AKV16;
        const uint32_t skh = smem_u32(S);
        const uint32_t skl = smem_u32(S + AKV16);
        const uint32_t svh = smem_u32(S + 2 * AKV16);
        const uint32_t svl = smem_u32(S + 3 * AKV16);
        const int k0 = t * 16;
#pragma unroll
        for (int i = 0; i < 2; i++) {
            int it = tid + i * 256;          // 0..511
            int r = it >> 5, c = (it & 31) * 8;
            const size_t g = (size_t)(k0 + r) * HD + c;
            const uint32_t off = (uint32_t)(r * ATS + c) * 2;
            cp_async16(skh + off, gkh + g);
            cp_async16(skl + off, gkl + g);
            cp_async16(svh + off, gvh + g);
            cp_async16(svl + off, gvl + g);
        }
        cp_commit();
    };

    issue_kv(0);

    for (int t = 0; t < NKT; t++) {
        if (t + 1 < NKT) { issue_kv(t + 1); cp_wait<1>(); }
        else             { cp_wait<0>(); }
        __syncthreads();

        __nv_bfloat16* S = KVbase + (size_t)(t & 1) * 4 * AKV16;
        __nv_bfloat16* SKh = S;
        __nv_bfloat16* SKl = S + AKV16;
        __nv_bfloat16* SVh = S + 2 * AKV16;
        __nv_bfloat16* SVl = S + 3 * AKV16;
        const int k0 = t * 16;

        // ---- S = Q K^T (16 q-rows x 16 keys per warp), split 3-MMA ----
        float sc[2][4];
#pragma unroll
        for (int n = 0; n < 2; n++)
#pragma unroll
            for (int e = 0; e < 4; e++) sc[n][e] = 0.0f;

#pragma unroll 4
        for (int ks = 0; ks < HD; ks += 16) {
            uint32_t aqh[4], aql[4], bh[4], bl[4];
            ldsm_x4(aqh, smem_u32(&SQh[qrow * ATS + ks + qc8]));
            ldsm_x4(aql, smem_u32(&SQl[qrow * ATS + ks + qc8]));
            ldsm_x4(bh, smem_u32(&SKh[krow_b * ATS + ks + kc8]));
            ldsm_x4(bl, smem_u32(&SKl[krow_b * ATS + ks + kc8]));
            mma_bf16(sc[0], aqh, bh);
            mma_bf16(sc[0], aqh, bl);
            mma_bf16(sc[0], aql, bh);
            mma_bf16(sc[1], aqh, bh + 2);
            mma_bf16(sc[1], aqh, bl + 2);
            mma_bf16(sc[1], aql, bh + 2);
        }

        // ---- soft-cap + causal mask (last 4 tiles overlap diagonal) ----
        const bool diag = (t >= NKT - 4);
        const int colb = k0 + 2 * (lane & 3);
        const int rowg = q0 + wq * 16 + (lane >> 2);
#pragma unroll
        for (int nt = 0; nt < 2; nt++) {
#pragma unroll
            for (int e = 0; e < 4; e++) {
                float z = 50.0f * tanhf(sc[nt][e] * cap_mul);
                if (diag) {
                    int col = colb + nt * 8 + (e & 1);
                    int row = rowg + ((e >> 1) << 3);
                    if (col > row) z = -INFINITY;
                }
                sc[nt][e] = z;
            }
        }

        // ---- online softmax (rows g and g+8) ----
        float rm0 = fmaxf(fmaxf(sc[0][0], sc[0][1]), fmaxf(sc[1][0], sc[1][1]));
        float rm1 = fmaxf(fmaxf(sc[0][2], sc[0][3]), fmaxf(sc[1][2], sc[1][3]));
        rm0 = fmaxf(rm0, __shfl_xor_sync(0xffffffffu, rm0, 1));
        rm0 = fmaxf(rm0, __shfl_xor_sync(0xffffffffu, rm0, 2));
        rm1 = fmaxf(rm1, __shfl_xor_sync(0xffffffffu, rm1, 1));
        rm1 = fmaxf(rm1, __shfl_xor_sync(0xffffffffu, rm1, 2));

        const float nm0 = fmaxf(m0, rm0);
        const float nm1 = fmaxf(m1, rm1);
        const float cr0 = __expf(m0 - nm0);
        const float cr1 = __expf(m1 - nm1);

        float ps0 = 0.0f, ps1 = 0.0f;
#pragma unroll
        for (int nt = 0; nt < 2; nt++) {
            float p0 = __expf(sc[nt][0] - nm0);
            float p1 = __expf(sc[nt][1] - nm0);
            float p2 = __expf(sc[nt][2] - nm1);
            float p3 = __expf(sc[nt][3] - nm1);
            sc[nt][0] = p0; sc[nt][1] = p1; sc[nt][2] = p2; sc[nt][3] = p3;
            ps0 += p0 + p1;
            ps1 += p2 + p3;
        }
        ps0 += __shfl_xor_sync(0xffffffffu, ps0, 1);
        ps0 += __shfl_xor_sync(0xffffffffu, ps0, 2);
        ps1 += __shfl_xor_sync(0xffffffffu, ps1, 1);
        ps1 += __shfl_xor_sync(0xffffffffu, ps1, 2);

        l0 = l0 * cr0 + ps0;
        l1 = l1 * cr1 + ps1;
        m0 = nm0; m1 = nm1;

#pragma unroll
        for (int n = 0; n < 32; n++) {
            acc[n][0] *= cr0; acc[n][1] *= cr0;
            acc[n][2] *= cr1; acc[n][3] *= cr1;
        }

        // ---- convert P (16x16) to split-bf16 A-fragment ----
        uint32_t ph[4], pl[4];
        {
            __nv_bfloat16 h0, lo0, h1, lo1;
#pragma unroll
            for (int half = 0; half < 2; half++) {
                split2(sc[half][0], h0, lo0);
                split2(sc[half][1], h1, lo1);
                ph[2 * half] = pack_bf2(h0, h1);
                pl[2 * half] = pack_bf2(lo0, lo1);
                split2(sc[half][2], h0, lo0);
                split2(sc[half][3], h1, lo1);
                ph[2 * half + 1] = pack_bf2(h0, h1);
                pl[2 * half + 1] = pack_bf2(lo0, lo1);
            }
        }

        // ---- acc += P V (16x16 @ 16x256), split 3-MMA ----
#pragma unroll
        for (int np = 0; np < 16; np++) {
            uint32_t bvh[4], bvl[4];
            const int vc = np * 16 + vc8;
            ldsm_x4_t(bvh, smem_u32(&SVh[vrow_b * ATS + vc]));
            ldsm_x4_t(bvl, smem_u32(&SVl[vrow_b * ATS + vc]));
            mma_bf16(acc[2 * np], ph, bvh);
            mma_bf16(acc[2 * np], ph, bvl);
            mma_bf16(acc[2 * np], pl, bvh);
            mma_bf16(acc[2 * np + 1], ph, bvh + 2);
            mma_bf16(acc[2 * np + 1], ph, bvl + 2);
            mma_bf16(acc[2 * np + 1], pl, bvh + 2);
        }
        __syncthreads();   // all warps done with this stage before reuse
    }

    // ---- epilogue: normalize, split to bf16 hi/lo, store ----
    const float il0 = 1.0f / l0;
    const float il1 = 1.0f / l1;
    const size_t rowA = (size_t)(q0 + wq * 16 + (lane >> 2));
    const size_t rowB = rowA + 8;
    const int cb = h * HD + 2 * (lane & 3);
#pragma unroll
    for (int nt = 0; nt < 32; nt++) {
        const int c = cb + nt * 8;
        float o0 = acc[nt][0] * il0, o1 = acc[nt][1] * il0;
        float o2 = acc[nt][2] * il1, o3 = acc[nt][3] * il1;
        __nv_bfloat16 h0, lo0, h1, lo1;
        split2(o0, h0, lo0); split2(o1, h1, lo1);
        *(uint32_t*)&g_att_hi[rowA * ATT_N + c] = pack_bf2(h0, h1);
        *(uint32_t*)&g_att_lo[rowA * ATT_N + c] = pack_bf2(lo0, lo1);
        split2(o2, h0, lo0); split2(o3, h1, lo1);
        *(uint32_t*)&g_att_hi[rowB * ATT_N + c] = pack_bf2(h0, h1);
        *(uint32_t*)&g_att_lo[rowB * ATT_N + c] = pack_bf2(lo0, lo1);
    }
}

// ---------------------------------------------------------------------------
// kernel_launch
// ---------------------------------------------------------------------------
extern "C" void kernel_launch(void* const* d_in, const int* in_sizes, int n_in,
                              void* d_out, int out_size)
{
    const int*   positions = (const int*)d_in[0];
    const float* hidden    = (const float*)d_in[1];
    const float* w_qkv     = (const float*)d_in[2];
    const float* w_o       = (const float*)d_in[3];
    float* out = (float*)d_out;

    float* qkv_ptr = nullptr;
    __nv_bfloat16 *hid_hi, *hid_lo, *wqkv_hi, *wqkv_lo, *wo_hi, *wo_lo, *att_hi, *att_lo;
    cudaGetSymbolAddress((void**)&qkv_ptr, g_qkv);
    cudaGetSymbolAddress((void**)&hid_hi, g_hid_hi);
    cudaGetSymbolAddress((void**)&hid_lo, g_hid_lo);
    cudaGetSymbolAddress((void**)&wqkv_hi, g_wqkv_hi);
    cudaGetSymbolAddress((void**)&wqkv_lo, g_wqkv_lo);
    cudaGetSymbolAddress((void**)&wo_hi, g_wo_hi);
    cudaGetSymbolAddress((void**)&wo_lo, g_wo_lo);
    cudaGetSymbolAddress((void**)&att_hi, g_att_hi);
    cudaGetSymbolAddress((void**)&att_lo, g_att_lo);

    // 0) Split inputs into bf16 hi/lo; build RoPE table
    {
        size_t n1 = (size_t)T_SEQ * HID;
        split_kernel<<<(unsigned)((n1 / 4 + 255) / 256), 256>>>(hidden, hid_hi, hid_lo, n1);
        size_t n2 = (size_t)HID * QKV_N;
        split_kernel<<<(unsigned)((n2 / 4 + 255) / 256), 256>>>(w_qkv, wqkv_hi, wqkv_lo, n2);
        size_t n3 = (size_t)ATT_N * HID;
        split_kernel<<<(unsigned)((n3 / 4 + 255) / 256), 256>>>(w_o, wo_hi, wo_lo, n3);
        rope_table_kernel<<<T_SEQ, 128>>>(positions);
    }

    // 1) QKV projection (pipelined split-bf16 tensor GEMM, R12 config)
    {
        cudaFuncSetAttribute(bgemm3_kernel,
                             cudaFuncAttributeMaxDynamicSharedMemorySize,
                             GEMM_SMEM_BYTES);
        dim3 grid(QKV_N / 128, T_SEQ / 128);
        bgemm3_kernel<<<grid, 256, GEMM_SMEM_BYTES>>>(
            hid_hi, hid_lo, wqkv_hi, wqkv_lo, qkv_ptr, T_SEQ, QKV_N, HID);
    }

    // 2) RoPE + split to head-major bf16 hi/lo Q/K/V
    rope_split_kernel<<<dim3(T_SEQ, NH + 2 * NKV), 128>>>();

    // 3) Flash attention: 2 GQA heads per CTA, 8 warps, shared KV
    {
        cudaFuncSetAttribute(attn_mma_kernel,
                             cudaFuncAttributeMaxDynamicSharedMemorySize,
                             ATT2_SMEM_BYTES);
        attn_mma_kernel<<<dim3(T_SEQ / 64, NKV), 256, ATT2_SMEM_BYTES>>>();
    }

    // 4) O projection (pipelined split-bf16 tensor GEMM, R12 config)
    {
        dim3 grid(HID / 128, T_SEQ / 128);
        bgemm3_kernel<<<grid, 256, GEMM_SMEM_BYTES>>>(
            att_hi, att_lo, wo_hi, wo_lo, out, T_SEQ, HID, ATT_N);
    }
}

// round 16
// speedup vs baseline: 1.1922x; 1.0553x over previous
#include <cuda_runtime.h>
#include <cuda_bf16.h>
#include <math.h>
#include <stdint.h>

// Problem constants
#define T_SEQ 2048
#define HID 3584
#define NH 16
#define NKV 8
#define HD 256
#define QKV_N ((NH + 2 * NKV) * HD)   // 8192
#define ATT_N (NH * HD)               // 4096

// Scratch (static device globals — no runtime allocation)
__device__ float g_qkv[(size_t)T_SEQ * QKV_N];    // 64 MB

// bf16 hi/lo splits for tensor-core GEMMs (weights row-major [K][N])
__device__ __nv_bfloat16 g_hid_hi[(size_t)T_SEQ * HID];
__device__ __nv_bfloat16 g_hid_lo[(size_t)T_SEQ * HID];
__device__ __nv_bfloat16 g_wqkv_hi[(size_t)HID * QKV_N];
__device__ __nv_bfloat16 g_wqkv_lo[(size_t)HID * QKV_N];
__device__ __nv_bfloat16 g_wo_hi[(size_t)ATT_N * HID];
__device__ __nv_bfloat16 g_wo_lo[(size_t)ATT_N * HID];
__device__ __nv_bfloat16 g_att_hi[(size_t)T_SEQ * ATT_N];
__device__ __nv_bfloat16 g_att_lo[(size_t)T_SEQ * ATT_N];

// head-major post-RoPE Q/K/V splits for attention: [head][t][d]
__device__ __nv_bfloat16 g_q_hi[(size_t)NH * T_SEQ * HD];
__device__ __nv_bfloat16 g_q_lo[(size_t)NH * T_SEQ * HD];
__device__ __nv_bfloat16 g_k_hi[(size_t)NKV * T_SEQ * HD];
__device__ __nv_bfloat16 g_k_lo[(size_t)NKV * T_SEQ * HD];
__device__ __nv_bfloat16 g_v_hi[(size_t)NKV * T_SEQ * HD];
__device__ __nv_bfloat16 g_v_lo[(size_t)NKV * T_SEQ * HD];

// RoPE cos/sin tables [t][i], i = 0..127
__device__ float g_rope_cos[(size_t)T_SEQ * 128];
__device__ float g_rope_sin[(size_t)T_SEQ * 128];

// ---------------------------------------------------------------------------
// helpers
// ---------------------------------------------------------------------------
__device__ __forceinline__ uint32_t smem_u32(const void* p) {
    return (uint32_t)__cvta_generic_to_shared(p);
}
__device__ __forceinline__ void ldsm_x4(uint32_t* r, uint32_t addr) {
    asm volatile("ldmatrix.sync.aligned.m8n8.x4.shared.b16 {%0,%1,%2,%3}, [%4];\n"
                 : "=r"(r[0]), "=r"(r[1]), "=r"(r[2]), "=r"(r[3]) : "r"(addr));
}
__device__ __forceinline__ void ldsm_x4_t(uint32_t* r, uint32_t addr) {
    asm volatile("ldmatrix.sync.aligned.m8n8.x4.trans.shared.b16 {%0,%1,%2,%3}, [%4];\n"
                 : "=r"(r[0]), "=r"(r[1]), "=r"(r[2]), "=r"(r[3]) : "r"(addr));
}
__device__ __forceinline__ void mma_bf16(float* c, const uint32_t* a, const uint32_t* b) {
    asm volatile(
        "mma.sync.aligned.m16n8k16.row.col.f32.bf16.bf16.f32 "
        "{%0,%1,%2,%3}, {%4,%5,%6,%7}, {%8,%9}, {%0,%1,%2,%3};\n"
        : "+f"(c[0]), "+f"(c[1]), "+f"(c[2]), "+f"(c[3])
        : "r"(a[0]), "r"(a[1]), "r"(a[2]), "r"(a[3]), "r"(b[0]), "r"(b[1]));
}
__device__ __forceinline__ void cp_async16(uint32_t smem_addr, const void* gptr) {
    asm volatile("cp.async.cg.shared.global [%0], [%1], 16;\n"
                 :: "r"(smem_addr), "l"(gptr));
}
__device__ __forceinline__ void cp_commit() {
    asm volatile("cp.async.commit_group;\n");
}
template <int N>
__device__ __forceinline__ void cp_wait() {
    asm volatile("cp.async.wait_group %0;\n" :: "n"(N));
}
__device__ __forceinline__ void split2(float x, __nv_bfloat16& h, __nv_bfloat16& l) {
    h = __float2bfloat16_rn(x);
    l = __float2bfloat16_rn(x - __bfloat162float(h));
}
__device__ __forceinline__ uint32_t pack_bf2(__nv_bfloat16 a, __nv_bfloat16 b) {
    __nv_bfloat162 t;
    t.x = a; t.y = b;
    uint32_t r;
    memcpy(&r, &t, 4);
    return r;
}

// ---------------------------------------------------------------------------
// Split fp32 -> bf16 hi + bf16 lo (residual). n must be multiple of 4.
// ---------------------------------------------------------------------------
__global__ void split_kernel(const float* __restrict__ x,
                             __nv_bfloat16* __restrict__ hi,
                             __nv_bfloat16* __restrict__ lo, size_t n)
{
    size_t i = ((size_t)blockIdx.x * blockDim.x + threadIdx.x) * 4;
    if (i >= n) return;
    float4 v = *(const float4*)(x + i);
    __nv_bfloat16 h[4], l[4];
    float vv[4] = {v.x, v.y, v.z, v.w};
#pragma unroll
    for (int j = 0; j < 4; j++) split2(vv[j], h[j], l[j]);
    *(uint2*)(hi + i) = *(uint2*)h;
    *(uint2*)(lo + i) = *(uint2*)l;
}

// ---------------------------------------------------------------------------
// Split-bf16 tensor-core GEMM, 3-stage cp.async pipeline, ONE barrier/iter.
// 128x128 tile, BK=32, 256 threads, warp tile 64x32.
// ---------------------------------------------------------------------------
#define AS_STRIDE 40
#define BS_STRIDE 136
#define G_AH 0
#define G_AL (128 * AS_STRIDE)
#define G_BH (2 * 128 * AS_STRIDE)
#define G_BL (2 * 128 * AS_STRIDE + 32 * BS_STRIDE)
#define G_STAGE (2 * 128 * AS_STRIDE + 2 * 32 * BS_STRIDE)   // 18944 elems
#define GEMM_SMEM_BYTES (3 * G_STAGE * 2)                    // 113664 B

__global__ __launch_bounds__(256) void bgemm3_kernel(
    const __nv_bfloat16* __restrict__ Ahi_g, const __nv_bfloat16* __restrict__ Alo_g,
    const __nv_bfloat16* __restrict__ Bhi_g, const __nv_bfloat16* __restrict__ Blo_g,
    float* __restrict__ C, int M, int N, int K)
{
    extern __shared__ __nv_bfloat16 gs[];

    const int tid = threadIdx.x;
    const int wid = tid >> 5;
    const int lane = tid & 31;
    const int wm = wid & 1;
    const int wn = wid >> 1;

    const int bm0 = blockIdx.y * 128;
    const int bn0 = blockIdx.x * 128;

    const int ch0 = tid, ch1 = tid + 256;
    const int ar0 = ch0 >> 2, ac0 = (ch0 & 3) * 8;
    const int ar1 = ch1 >> 2, ac1 = (ch1 & 3) * 8;
    const int br0 = ch0 >> 4, bc0 = (ch0 & 15) * 8;
    const int br1 = ch1 >> 4, bc1 = (ch1 & 15) * 8;

    const int NIT = K / 32;

    auto issue_stage = [&](int stage, int k0) {
        __nv_bfloat16* S = gs + stage * G_STAGE;
        uint32_t sAh = smem_u32(S + G_AH);
        uint32_t sAl = smem_u32(S + G_AL);
        uint32_t sBh = smem_u32(S + G_BH);
        uint32_t sBl = smem_u32(S + G_BL);
        cp_async16(sAh + (ar0 * AS_STRIDE + ac0) * 2, Ahi_g + (size_t)(bm0 + ar0) * K + k0 + ac0);
        cp_async16(sAh + (ar1 * AS_STRIDE + ac1) * 2, Ahi_g + (size_t)(bm0 + ar1) * K + k0 + ac1);
        cp_async16(sAl + (ar0 * AS_STRIDE + ac0) * 2, Alo_g + (size_t)(bm0 + ar0) * K + k0 + ac0);
        cp_async16(sAl + (ar1 * AS_STRIDE + ac1) * 2, Alo_g + (size_t)(bm0 + ar1) * K + k0 + ac1);
        cp_async16(sBh + (br0 * BS_STRIDE + bc0) * 2, Bhi_g + (size_t)(k0 + br0) * N + bn0 + bc0);
        cp_async16(sBh + (br1 * BS_STRIDE + bc1) * 2, Bhi_g + (size_t)(k0 + br1) * N + bn0 + bc1);
        cp_async16(sBl + (br0 * BS_STRIDE + bc0) * 2, Blo_g + (size_t)(k0 + br0) * N + bn0 + bc0);
        cp_async16(sBl + (br1 * BS_STRIDE + bc1) * 2, Blo_g + (size_t)(k0 + br1) * N + bn0 + bc1);
        cp_commit();
    };

    float c[4][4][4] = {};

    // prologue: 2 stages in flight
    issue_stage(0, 0);
    issue_stage(1, 32);

    for (int it = 0; it < NIT; it++) {
        const int s = it % 3;

        // wait for stage `it`; keep at most one younger group in flight
        if (it + 1 < NIT) cp_wait<1>(); else cp_wait<0>();
        __syncthreads();
        // All warps have finished reading stage (it-1)%3 == (it+2)%3 at this
        // point, so refilling it is race-free — no trailing barrier needed.
        if (it + 2 < NIT) issue_stage((it + 2) % 3, (it + 2) * 32);

        const __nv_bfloat16* S = gs + s * G_STAGE;
        const __nv_bfloat16* Ah = S + G_AH;
        const __nv_bfloat16* Al = S + G_AL;
        const __nv_bfloat16* Bh = S + G_BH;
        const __nv_bfloat16* Bl = S + G_BL;

#pragma unroll
        for (int ks = 0; ks < 32; ks += 16) {
            uint32_t ah[4][4], al[4][4], bh[4][2], bl[4][2];
            const int arow = wm * 64 + (lane & 15);
            const int acol = ks + (lane >> 4) * 8;
#pragma unroll
            for (int mi = 0; mi < 4; mi++) {
                ldsm_x4(ah[mi], smem_u32(Ah + (arow + mi * 16) * AS_STRIDE + acol));
                ldsm_x4(al[mi], smem_u32(Al + (arow + mi * 16) * AS_STRIDE + acol));
            }
            const int brow = ks + (lane & 15);
#pragma unroll
            for (int nj = 0; nj < 2; nj++) {
                const int bcol = wn * 32 + nj * 16 + (lane >> 4) * 8;
                uint32_t r[4];
                ldsm_x4_t(r, smem_u32(Bh + brow * BS_STRIDE + bcol));
                bh[nj * 2][0] = r[0]; bh[nj * 2][1] = r[1];
                bh[nj * 2 + 1][0] = r[2]; bh[nj * 2 + 1][1] = r[3];
                ldsm_x4_t(r, smem_u32(Bl + brow * BS_STRIDE + bcol));
                bl[nj * 2][0] = r[0]; bl[nj * 2][1] = r[1];
                bl[nj * 2 + 1][0] = r[2]; bl[nj * 2 + 1][1] = r[3];
            }
#pragma unroll
            for (int mi = 0; mi < 4; mi++)
#pragma unroll
                for (int ni = 0; ni < 4; ni++) {
                    mma_bf16(c[mi][ni], ah[mi], bh[ni]);
                    mma_bf16(c[mi][ni], ah[mi], bl[ni]);
                    mma_bf16(c[mi][ni], al[mi], bh[ni]);
                }
        }
    }

    const int gid = lane >> 2, tig = lane & 3;
#pragma unroll
    for (int mi = 0; mi < 4; mi++) {
        const int r0 = bm0 + wm * 64 + mi * 16 + gid;
#pragma unroll
        for (int ni = 0; ni < 4; ni++) {
            const int cc = bn0 + wn * 32 + ni * 8 + tig * 2;
            *(float2*)&C[(size_t)r0 * N + cc] = make_float2(c[mi][ni][0], c[mi][ni][1]);
            *(float2*)&C[(size_t)(r0 + 8) * N + cc] = make_float2(c[mi][ni][2], c[mi][ni][3]);
        }
    }
}

// ---------------------------------------------------------------------------
// RoPE table: one sincos per (t, i).
// ---------------------------------------------------------------------------
__global__ void rope_table_kernel(const int* __restrict__ positions)
{
    const int t = blockIdx.x;
    const int i = threadIdx.x;
    const float pos = (float)positions[t];
    const float inv_freq = powf(10000.0f, -(float)i * (1.0f / 128.0f));
    float s, c;
    sincosf(pos * inv_freq, &s, &c);
    g_rope_cos[(size_t)t * 128 + i] = c;
    g_rope_sin[(size_t)t * 128 + i] = s;
}

// ---------------------------------------------------------------------------
// RoPE + split to head-major bf16 hi/lo Q/K/V (table-driven).
// ---------------------------------------------------------------------------
__global__ void rope_split_kernel()
{
    const int t = blockIdx.x;
    const int hh = blockIdx.y;
    const int i = threadIdx.x;

    float y1, y2;
    __nv_bfloat16 *dst_hi, *dst_lo;

    if (hh < NH + NKV) {
        const int head_off = (hh < NH) ? hh : (NH + (hh - NH));
        const float* src = g_qkv + (size_t)t * QKV_N + head_off * HD;
        const float c = g_rope_cos[(size_t)t * 128 + i];
        const float s = g_rope_sin[(size_t)t * 128 + i];
        const float x1 = src[i];
        const float x2 = src[i + 128];
        y1 = x1 * c - x2 * s;
        y2 = x2 * c + x1 * s;
        if (hh < NH) {
            dst_hi = g_q_hi + ((size_t)hh * T_SEQ + t) * HD;
            dst_lo = g_q_lo + ((size_t)hh * T_SEQ + t) * HD;
        } else {
            const int kvh = hh - NH;
            dst_hi = g_k_hi + ((size_t)kvh * T_SEQ + t) * HD;
            dst_lo = g_k_lo + ((size_t)kvh * T_SEQ + t) * HD;
        }
    } else {
        const int vh = hh - (NH + NKV);
        const float* src = g_qkv + (size_t)t * QKV_N + (NH + NKV + vh) * HD;
        y1 = src[i];
        y2 = src[i + 128];
        dst_hi = g_v_hi + ((size_t)vh * T_SEQ + t) * HD;
        dst_lo = g_v_lo + ((size_t)vh * T_SEQ + t) * HD;
    }

    __nv_bfloat16 h1, l1, h2, l2;
    split2(y1, h1, l1);
    split2(y2, h2, l2);
    dst_hi[i] = h1;        dst_lo[i] = l1;
    dst_hi[i + 128] = h2;  dst_lo[i + 128] = l2;
}

// ---------------------------------------------------------------------------
// Tensor-core flash attention (split-bf16) with 2-stage cp.async K/V pipeline
// (R12 config: 1 head/CTA, 4 warps, 32-key KV tiles — best measured).
// ---------------------------------------------------------------------------
#define ATS 264
#define AQ_TILE (64 * ATS)
#define AKV_TILE (32 * ATS)
#define ATT2_SMEM_BYTES ((2 * AQ_TILE + 8 * AKV_TILE) * 2)   // 202752

__global__ __launch_bounds__(128, 1) void attn_mma_kernel()
{
    extern __shared__ __nv_bfloat16 sb[];
    __nv_bfloat16* SQh = sb;
    __nv_bfloat16* SQl = sb + AQ_TILE;

    const int tid = threadIdx.x;
    const int lane = tid & 31;
    const int warp = tid >> 5;
    const int qt = (int)gridDim.x - 1 - (int)blockIdx.x;
    const int h = blockIdx.y;
    const int kvh = h >> 1;
    const int q0 = qt * 64;

    {
        const __nv_bfloat16* gqh = g_q_hi + ((size_t)h * T_SEQ + q0) * HD;
        const __nv_bfloat16* gql = g_q_lo + ((size_t)h * T_SEQ + q0) * HD;
        for (int it = tid; it < 64 * 32; it += 128) {
            int r = it >> 5, c = (it & 31) * 8;
            *(float4*)&SQh[r * ATS + c] = *(const float4*)(gqh + (size_t)r * HD + c);
            *(float4*)&SQl[r * ATS + c] = *(const float4*)(gql + (size_t)r * HD + c);
        }
    }

    float acc[32][4];
#pragma unroll
    for (int n = 0; n < 32; n++)
#pragma unroll
        for (int e = 0; e < 4; e++) acc[n][e] = 0.0f;
    float m0 = -INFINITY, m1 = -INFINITY, l0 = 0.0f, l1 = 0.0f;

    const float cap_mul = 0.0625f / 50.0f;

    const int qrow = warp * 16 + (lane & 15);
    const int qc8 = (lane >> 4) << 3;
    const int krow_b = ((lane >> 4) << 3) + (lane & 7);
    const int kc8 = ((lane >> 3) & 1) << 3;
    const int vrow_b = lane & 15;
    const int vc8 = (lane >> 4) << 3;

    const __nv_bfloat16* gkh = g_k_hi + (size_t)kvh * T_SEQ * HD;
    const __nv_bfloat16* gkl = g_k_lo + (size_t)kvh * T_SEQ * HD;
    const __nv_bfloat16* gvh = g_v_hi + (size_t)kvh * T_SEQ * HD;
    const __nv_bfloat16* gvl = g_v_lo + (size_t)kvh * T_SEQ * HD;

    const int NKT = 2 * (qt + 1);

    auto issue_kv = [&](int t) {
        __nv_bfloat16* S = sb + 2 * AQ_TILE + (size_t)(t & 1) * 4 * AKV_TILE;
        const uint32_t skh = smem_u32(S);
        const uint32_t skl = smem_u32(S + AKV_TILE);
        const uint32_t svh = smem_u32(S + 2 * AKV_TILE);
        const uint32_t svl = smem_u32(S + 3 * AKV_TILE);
        const int k0 = t * 32;
#pragma unroll
        for (int i = 0; i < 8; i++) {
            int it = tid + i * 128;
            int r = it >> 5, c = (it & 31) * 8;
            const size_t g = (size_t)(k0 + r) * HD + c;
            const uint32_t off = (uint32_t)(r * ATS + c) * 2;
            cp_async16(skh + off, gkh + g);
            cp_async16(skl + off, gkl + g);
            cp_async16(svh + off, gvh + g);
            cp_async16(svl + off, gvl + g);
        }
        cp_commit();
    };

    issue_kv(0);

    for (int t = 0; t < NKT; t++) {
        if (t + 1 < NKT) { issue_kv(t + 1); cp_wait<1>(); }
        else             { cp_wait<0>(); }
        __syncthreads();

        __nv_bfloat16* S = sb + 2 * AQ_TILE + (size_t)(t & 1) * 4 * AKV_TILE;
        __nv_bfloat16* SKh = S;
        __nv_bfloat16* SKl = S + AKV_TILE;
        __nv_bfloat16* SVh = S + 2 * AKV_TILE;
        __nv_bfloat16* SVl = S + 3 * AKV_TILE;
        const int k0 = t * 32;

        float sc[4][4];
#pragma unroll
        for (int n = 0; n < 4; n++)
#pragma unroll
            for (int e = 0; e < 4; e++) sc[n][e] = 0.0f;

#pragma unroll 4
        for (int ks = 0; ks < HD; ks += 16) {
            uint32_t aqh[4], aql[4];
            ldsm_x4(aqh, smem_u32(&SQh[qrow * ATS + ks + qc8]));
            ldsm_x4(aql, smem_u32(&SQl[qrow * ATS + ks + qc8]));
#pragma unroll
            for (int p4 = 0; p4 < 2; p4++) {
                uint32_t bh[4], bl[4];
                const int kr = p4 * 16 + krow_b;
                ldsm_x4(bh, smem_u32(&SKh[kr * ATS + ks + kc8]));
                ldsm_x4(bl, smem_u32(&SKl[kr * ATS + ks + kc8]));
                mma_bf16(sc[2 * p4], aqh, bh);
                mma_bf16(sc[2 * p4], aqh, bl);
                mma_bf16(sc[2 * p4], aql, bh);
                mma_bf16(sc[2 * p4 + 1], aqh, bh + 2);
                mma_bf16(sc[2 * p4 + 1], aqh, bl + 2);
                mma_bf16(sc[2 * p4 + 1], aql, bh + 2);
            }
        }

        const bool diag = (t >= NKT - 2);
        const int colb = k0 + 2 * (lane & 3);
        const int rowg = q0 + warp * 16 + (lane >> 2);
#pragma unroll
        for (int nt = 0; nt < 4; nt++) {
#pragma unroll
            for (int e = 0; e < 4; e++) {
                float z = 50.0f * tanhf(sc[nt][e] * cap_mul);
                if (diag) {
                    int col = colb + nt * 8 + (e & 1);
                    int row = rowg + ((e >> 1) << 3);
                    if (col > row) z = -INFINITY;
                }
                sc[nt][e] = z;
            }
        }

        float rm0 = -INFINITY, rm1 = -INFINITY;
#pragma unroll
        for (int nt = 0; nt < 4; nt++) {
            rm0 = fmaxf(rm0, fmaxf(sc[nt][0], sc[nt][1]));
            rm1 = fmaxf(rm1, fmaxf(sc[nt][2], sc[nt][3]));
        }
        rm0 = fmaxf(rm0, __shfl_xor_sync(0xffffffffu, rm0, 1));
        rm0 = fmaxf(rm0, __shfl_xor_sync(0xffffffffu, rm0, 2));
        rm1 = fmaxf(rm1, __shfl_xor_sync(0xffffffffu, rm1, 1));
        rm1 = fmaxf(rm1, __shfl_xor_sync(0xffffffffu, rm1, 2));

        const float nm0 = fmaxf(m0, rm0);
        const float nm1 = fmaxf(m1, rm1);
        const float cr0 = __expf(m0 - nm0);
        const float cr1 = __expf(m1 - nm1);

        float ps0 = 0.0f, ps1 = 0.0f;
#pragma unroll
        for (int nt = 0; nt < 4; nt++) {
            float p0 = __expf(sc[nt][0] - nm0);
            float p1 = __expf(sc[nt][1] - nm0);
            float p2 = __expf(sc[nt][2] - nm1);
            float p3 = __expf(sc[nt][3] - nm1);
            sc[nt][0] = p0; sc[nt][1] = p1; sc[nt][2] = p2; sc[nt][3] = p3;
            ps0 += p0 + p1;
            ps1 += p2 + p3;
        }
        ps0 += __shfl_xor_sync(0xffffffffu, ps0, 1);
        ps0 += __shfl_xor_sync(0xffffffffu, ps0, 2);
        ps1 += __shfl_xor_sync(0xffffffffu, ps1, 1);
        ps1 += __shfl_xor_sync(0xffffffffu, ps1, 2);

        l0 = l0 * cr0 + ps0;
        l1 = l1 * cr1 + ps1;
        m0 = nm0; m1 = nm1;

#pragma unroll
        for (int n = 0; n < 32; n++) {
            acc[n][0] *= cr0; acc[n][1] *= cr0;
            acc[n][2] *= cr1; acc[n][3] *= cr1;
        }

        uint32_t ph[2][4], pl[2][4];
#pragma unroll
        for (int j = 0; j < 2; j++) {
            __nv_bfloat16 h0, lo0, h1, lo1;
#pragma unroll
            for (int half = 0; half < 2; half++) {
                const int nt = 2 * j + half;
                split2(sc[nt][0], h0, lo0);
                split2(sc[nt][1], h1, lo1);
                ph[j][2 * half] = pack_bf2(h0, h1);
                pl[j][2 * half] = pack_bf2(lo0, lo1);
                split2(sc[nt][2], h0, lo0);
                split2(sc[nt][3], h1, lo1);
                ph[j][2 * half + 1] = pack_bf2(h0, h1);
                pl[j][2 * half + 1] = pack_bf2(lo0, lo1);
            }
        }

#pragma unroll
        for (int kk = 0; kk < 2; kk++) {
            const int vr = kk * 16 + vrow_b;
#pragma unroll
            for (int np = 0; np < 16; np++) {
                uint32_t bvh[4], bvl[4];
                const int vc = np * 16 + vc8;
                ldsm_x4_t(bvh, smem_u32(&SVh[vr * ATS + vc]));
                ldsm_x4_t(bvl, smem_u32(&SVl[vr * ATS + vc]));
                mma_bf16(acc[2 * np], ph[kk], bvh);
                mma_bf16(acc[2 * np], ph[kk], bvl);
                mma_bf16(acc[2 * np], pl[kk], bvh);
                mma_bf16(acc[2 * np + 1], ph[kk], bvh + 2);
                mma_bf16(acc[2 * np + 1], ph[kk], bvl + 2);
                mma_bf16(acc[2 * np + 1], pl[kk], bvh + 2);
            }
        }
        __syncthreads();
    }

    const float il0 = 1.0f / l0;
    const float il1 = 1.0f / l1;
    const size_t rowA = (size_t)(q0 + warp * 16 + (lane >> 2));
    const size_t rowB = rowA + 8;
    const int cb = h * HD + 2 * (lane & 3);
#pragma unroll
    for (int nt = 0; nt < 32; nt++) {
        const int c = cb + nt * 8;
        float o0 = acc[nt][0] * il0, o1 = acc[nt][1] * il0;
        float o2 = acc[nt][2] * il1, o3 = acc[nt][3] * il1;
        __nv_bfloat16 h0, lo0, h1, lo1;
        split2(o0, h0, lo0); split2(o1, h1, lo1);
        *(uint32_t*)&g_att_hi[rowA * ATT_N + c] = pack_bf2(h0, h1);
        *(uint32_t*)&g_att_lo[rowA * ATT_N + c] = pack_bf2(lo0, lo1);
        split2(o2, h0, lo0); split2(o3, h1, lo1);
        *(uint32_t*)&g_att_hi[rowB * ATT_N + c] = pack_bf2(h0, h1);
        *(uint32_t*)&g_att_lo[rowB * ATT_N + c] = pack_bf2(lo0, lo1);
    }
}

// ---------------------------------------------------------------------------
// kernel_launch
// ---------------------------------------------------------------------------
extern "C" void kernel_launch(void* const* d_in, const int* in_sizes, int n_in,
                              void* d_out, int out_size)
{
    const int*   positions = (const int*)d_in[0];
    const float* hidden    = (const float*)d_in[1];
    const float* w_qkv     = (const float*)d_in[2];
    const float* w_o       = (const float*)d_in[3];
    float* out = (float*)d_out;

    float* qkv_ptr = nullptr;
    __nv_bfloat16 *hid_hi, *hid_lo, *wqkv_hi, *wqkv_lo, *wo_hi, *wo_lo, *att_hi, *att_lo;
    cudaGetSymbolAddress((void**)&qkv_ptr, g_qkv);
    cudaGetSymbolAddress((void**)&hid_hi, g_hid_hi);
    cudaGetSymbolAddress((void**)&hid_lo, g_hid_lo);
    cudaGetSymbolAddress((void**)&wqkv_hi, g_wqkv_hi);
    cudaGetSymbolAddress((void**)&wqkv_lo, g_wqkv_lo);
    cudaGetSymbolAddress((void**)&wo_hi, g_wo_hi);
    cudaGetSymbolAddress((void**)&wo_lo, g_wo_lo);
    cudaGetSymbolAddress((void**)&att_hi, g_att_hi);
    cudaGetSymbolAddress((void**)&att_lo, g_att_lo);

    // 0) Split inputs into bf16 hi/lo; build RoPE table
    {
        size_t n1 = (size_t)T_SEQ * HID;
        split_kernel<<<(unsigned)((n1 / 4 + 255) / 256), 256>>>(hidden, hid_hi, hid_lo, n1);
        size_t n2 = (size_t)HID * QKV_N;
        split_kernel<<<(unsigned)((n2 / 4 + 255) / 256), 256>>>(w_qkv, wqkv_hi, wqkv_lo, n2);
        size_t n3 = (size_t)ATT_N * HID;
        split_kernel<<<(unsigned)((n3 / 4 + 255) / 256), 256>>>(w_o, wo_hi, wo_lo, n3);
        rope_table_kernel<<<T_SEQ, 128>>>(positions);
    }

    // 1) QKV projection (3-stage pipelined split-bf16 tensor GEMM)
    {
        cudaFuncSetAttribute(bgemm3_kernel,
                             cudaFuncAttributeMaxDynamicSharedMemorySize,
                             GEMM_SMEM_BYTES);
        dim3 grid(QKV_N / 128, T_SEQ / 128);
        bgemm3_kernel<<<grid, 256, GEMM_SMEM_BYTES>>>(
            hid_hi, hid_lo, wqkv_hi, wqkv_lo, qkv_ptr, T_SEQ, QKV_N, HID);
    }

    // 2) RoPE + split to head-major bf16 hi/lo Q/K/V
    rope_split_kernel<<<dim3(T_SEQ, NH + 2 * NKV), 128>>>();

    // 3) Pipelined tensor-core flash attention -> att_hi/att_lo (R12 config)
    {
        cudaFuncSetAttribute(attn_mma_kernel,
                             cudaFuncAttributeMaxDynamicSharedMemorySize,
                             ATT2_SMEM_BYTES);
        attn_mma_kernel<<<dim3(T_SEQ / 64, NH), 128, ATT2_SMEM_BYTES>>>();
    }

    // 4) O projection (3-stage pipelined split-bf16 tensor GEMM)
    {
        dim3 grid(HID / 128, T_SEQ / 128);
        bgemm3_kernel<<<grid, 256, GEMM_SMEM_BYTES>>>(
            att_hi, att_lo, wo_hi, wo_lo, out, T_SEQ, HID, ATT_N);
    }
}